// round 8
// baseline (speedup 1.0000x reference)
#include <cuda_runtime.h>
#include <cstdint>
#include <mma.h>
#include <math.h>

using namespace nvcuda;

namespace {
constexpr int NV = 512;   // nodes
constexpr int C  = 256;   // channels
constexpr int MT = 64;    // j-tile rows
constexpr int LDA = 264;  // padded A leading dim (floats)
constexpr int NWARP = 8;  // 256 threads
constexpr int NCHUNK = C / 8;   // 32 k-chunks of 8
constexpr int BUF_FLOATS = 256 * 8;  // one slab: 256 out-cols x 8 k

// smem layout (floats)
constexpr int SM_A   = 0;                     // [MT][LDA]        = 16896
constexpr int SM_Q   = SM_A + MT * LDA;       // [MT][C]          = 16384
constexpr int SM_VE  = SM_Q + MT * C;         // [MT][C]          = 16384
constexpr int SM_B   = SM_VE + MT * C;        // 3 slabs          = 6144
constexpr int SM_N   = SM_B + 3 * BUF_FLOATS; // [C]
constexpr int SM_BK  = SM_N + C;              // [C]
constexpr int SM_SC  = SM_BK + C;             // [MT]
constexpr int SM_P   = SM_SC + MT;            // [MT]
constexpr int SM_RED = SM_P + MT;             // [NWARP]
constexpr int SMEM_FLOATS = SM_RED + NWARP;
constexpr int SMEM_BYTES  = SMEM_FLOATS * 4;  // ~225.8 KB (< 227 KB cap)
}

// pre-rounded tf32 weights: [Wq | Wk | Wv]
__device__ float g_wt[3 * C * C];

__device__ __forceinline__ float to_tf32(float x) {
    float y; asm("cvt.rna.tf32.f32 %0, %1;" : "=f"(y) : "f"(x)); return y;
}
__device__ __forceinline__ uint32_t smem_u32(const void* p) {
    uint32_t a;
    asm("{ .reg .u64 t; cvta.to.shared.u64 t, %1; cvt.u32.u64 %0, t; }" : "=r"(a) : "l"(p));
    return a;
}
__device__ __forceinline__ void cp_async16(uint32_t dst, const void* src) {
    asm volatile("cp.async.ca.shared.global [%0], [%1], 16;" :: "r"(dst), "l"(src));
}
#define CP_COMMIT() asm volatile("cp.async.commit_group;" ::: "memory")
#define CP_WAIT(n)  asm volatile("cp.async.wait_group %0;" :: "n"(n) : "memory")

__global__ __launch_bounds__(256) void prep_weights(
    const float* __restrict__ Wq, const float* __restrict__ Wk, const float* __restrict__ Wv)
{
    const int idx = (blockIdx.x * 256 + threadIdx.x) * 4;
    const float* src = (blockIdx.y == 0) ? Wq : (blockIdx.y == 1 ? Wk : Wv);
    float4 t = *reinterpret_cast<const float4*>(src + idx);
    t.x = to_tf32(t.x); t.y = to_tf32(t.y); t.z = to_tf32(t.z); t.w = to_tf32(t.w);
    *reinterpret_cast<float4*>(g_wt + (size_t)blockIdx.y * C * C + idx) = t;
}

struct AccFrags {
    wmma::fragment<wmma::accumulator, 16, 16, 8, float> acc[4][2];
};

// (64x256 tf32 A-tile in smem) @ W^T with W streamed through a 3-buffer
// cp.async slab ring in smem. Warp wid -> output cols [wid*32, wid*32+32).
// Slab layout: col-major per chunk, elem(k,n) at sB[n*8 + k], ldm = 8.
__device__ __forceinline__ void gemm_slab(AccFrags& f, const float* sA, const float* sB,
                                          uint32_t smbB, const float* __restrict__ Wg,
                                          int wid, int tid) {
#pragma unroll
    for (int m = 0; m < 4; m++)
#pragma unroll
        for (int nn = 0; nn < 2; nn++) wmma::fill_fragment(f.acc[m][nn], 0.0f);

    // issue one 8-KB chunk: 512 float4, 2 per thread
    auto issue = [&](int c) {
        const int k0 = c * 8;
        const uint32_t bufb = smbB + (uint32_t)(c % 3) * (BUF_FLOATS * 4);
#pragma unroll
        for (int h = 0; h < 2; h++) {
            const int idx = tid + h * 256;
            const int n = idx >> 1, q = idx & 1;
            cp_async16(bufb + (uint32_t)(n * 32 + q * 16),
                       Wg + (size_t)n * C + k0 + q * 4);
        }
        CP_COMMIT();
    };
    issue(0);
    issue(1);

    wmma::fragment<wmma::matrix_a, 16, 16, 8, wmma::precision::tf32, wmma::row_major> af[4];
    wmma::fragment<wmma::matrix_b, 16, 16, 8, wmma::precision::tf32, wmma::col_major> bf[2];

    for (int kc = 0; kc < NCHUNK; kc++) {
        CP_WAIT(1);            // own copies of chunk kc complete (2 groups always pending)
        __syncthreads();       // all threads' chunk kc visible; buf (kc+2)%3 free
        if (kc + 2 < NCHUNK) issue(kc + 2);
        else CP_COMMIT();      // empty group keeps the pending-count invariant

        const float* B = sB + (kc % 3) * BUF_FLOATS + (wid * 32) * 8;
        wmma::load_matrix_sync(bf[0], B, 8);
        wmma::load_matrix_sync(bf[1], B + 16 * 8, 8);
#pragma unroll
        for (int m = 0; m < 4; m++)
            wmma::load_matrix_sync(af[m], sA + m * 16 * LDA + kc * 8, LDA);
#pragma unroll
        for (int m = 0; m < 4; m++)
#pragma unroll
            for (int nn = 0; nn < 2; nn++)
                wmma::mma_sync(f.acc[m][nn], af[m], bf[nn], f.acc[m][nn]);
    }
    CP_WAIT(0);
    __syncthreads();           // slab buffers reusable by next GEMM
}

__device__ __forceinline__ void frag_store(AccFrags& f, float* dst, int ldm, int wid) {
#pragma unroll
    for (int m = 0; m < 4; m++)
#pragma unroll
        for (int nn = 0; nn < 2; nn++)
            wmma::store_matrix_sync(dst + m * 16 * ldm + wid * 32 + nn * 16,
                                    f.acc[m][nn], ldm, wmma::mem_row_major);
}

// A[j][c] = tf32(n_i[c] * n_j[c] * s[i, j0+j, c])
__device__ __forceinline__ void build_tile(float* sA, const float* sn,
                                           const float* __restrict__ nmat,
                                           const float* __restrict__ s,
                                           int i, int j0, int tid) {
#pragma unroll 4
    for (int idx = tid; idx < MT * (C / 4); idx += 256) {
        const int j  = idx >> 6;
        const int c4 = (idx & 63) * 4;
        const float4 n4  = *reinterpret_cast<const float4*>(nmat + (size_t)(j0 + j) * C + c4);
        const float4 s4  = *reinterpret_cast<const float4*>(s + ((size_t)i * NV + j0 + j) * C + c4);
        const float4 sn4 = *reinterpret_cast<const float4*>(sn + c4);
        float4 r;
        r.x = to_tf32(sn4.x * n4.x * s4.x);
        r.y = to_tf32(sn4.y * n4.y * s4.y);
        r.z = to_tf32(sn4.z * n4.z * s4.z);
        r.w = to_tf32(sn4.w * n4.w * s4.w);
        *reinterpret_cast<float4*>(sA + j * LDA + c4) = r;
    }
}

__global__ __launch_bounds__(256, 1) void fused_kernel(
    const float* __restrict__ nmat, const float* __restrict__ s, const float* __restrict__ v,
    const float* __restrict__ bq, const float* __restrict__ bk, const float* __restrict__ bv,
    float* __restrict__ out)
{
    extern __shared__ float sm[];
    float* sA  = sm + SM_A;
    float* sQ  = sm + SM_Q;
    float* sVe = sm + SM_VE;
    float* sB  = sm + SM_B;
    float* sn  = sm + SM_N;
    float* sbk = sm + SM_BK;
    float* ssc = sm + SM_SC;
    float* sp  = sm + SM_P;
    float* red = sm + SM_RED;
    const uint32_t smbB = smem_u32(sB);

    const int i = blockIdx.x;
    const int tid = threadIdx.x;
    const int wid = tid >> 5, lane = tid & 31;

    sn[tid]  = nmat[(size_t)i * C + tid];
    sbk[tid] = bk[tid];
    const float bqd = bq[tid], bvd = bv[tid];

    float m_run = -1e30f, l_run = 0.0f, xacc = 0.0f;

    for (int jt = 0; jt < NV / MT; jt++) {
        const int j0 = jt * MT;
        __syncthreads();                       // prev-iter smem readers done
        build_tile(sA, sn, nmat, s, i, j0, tid);
        __syncthreads();

        AccFrags f;
        gemm_slab(f, sA, sB, smbB, g_wt,             wid, tid); frag_store(f, sQ,  C,   wid); // Q
        gemm_slab(f, sA, sB, smbB, g_wt + 2 * C * C, wid, tid); frag_store(f, sVe, C,   wid); // V
        gemm_slab(f, sA, sB, smbB, g_wt + 1 * C * C, wid, tid);                               // K
        __syncthreads();                       // all warps done reading sA
        frag_store(f, sA, LDA, wid);           // Gk overwrites A

        // fold bq and v^2 into q-tilde (thread owns channel tid)
        {
            const float* vrow = v + ((size_t)i * NV + j0) * C + tid;
#pragma unroll 4
            for (int j = 0; j < MT; j++) {
                const float vv = vrow[(size_t)j * C];
                sQ[j * C + tid] = (sQ[j * C + tid] + bqd) * vv * vv;
            }
        }
        __syncthreads();                       // Gk + q~ visible

        // scores: warp handles MT/NWARP rows
#pragma unroll
        for (int r = 0; r < MT / NWARP; r++) {
            const int j = wid * (MT / NWARP) + r;
            float p = 0.0f;
#pragma unroll 4
            for (int d = lane; d < C; d += 32)
                p += sQ[j * C + d] * (sA[j * LDA + d] + sbk[d]);
#pragma unroll
            for (int o = 16; o > 0; o >>= 1) p += __shfl_xor_sync(0xffffffffu, p, o);
            if (lane == 0) ssc[j] = p * 0.0625f;   // 1/sqrt(256)
        }
        __syncthreads();

        // online softmax update (replicated scalar math on all threads)
        float tm = -1e30f;
#pragma unroll 8
        for (int j = 0; j < MT; j++) tm = fmaxf(tm, ssc[j]);
        const float m_new = fmaxf(m_run, tm);
        const float scl = __expf(m_run - m_new);
        xacc *= scl; l_run *= scl;
        if (tid < MT) sp[tid] = __expf(ssc[tid] - m_new);
        __syncthreads();
        float ls = 0.0f;
#pragma unroll 8
        for (int j = 0; j < MT; j++) ls += sp[j];
        l_run += ls;
        m_run = m_new;

        // V accumulate: x_tid += sum_j p_j (Gv[j,tid]+bv) v[j,tid]
        {
            const float* vrow = v + ((size_t)i * NV + j0) * C + tid;
#pragma unroll 4
            for (int j = 0; j < MT; j++)
                xacc += sp[j] * (sVe[j * C + tid] + bvd) * vrow[(size_t)j * C];
        }
    }

    // residual + L2 normalize
    const float x = xacc / l_run + sn[tid];
    float sq = x * x;
#pragma unroll
    for (int o = 16; o > 0; o >>= 1) sq += __shfl_xor_sync(0xffffffffu, sq, o);
    __syncthreads();
    if (lane == 0) red[wid] = sq;
    __syncthreads();
    float tot = 0.0f;
#pragma unroll
    for (int w = 0; w < NWARP; w++) tot += red[w];
    out[(size_t)i * C + tid] = x * rsqrtf(tot);
}

extern "C" void kernel_launch(void* const* d_in, const int* in_sizes, int n_in,
                              void* d_out, int out_size) {
    const float* nmat = (const float*)d_in[0];
    const float* s    = (const float*)d_in[1];
    const float* v    = (const float*)d_in[2];
    const float* Wq   = (const float*)d_in[3];
    const float* bq   = (const float*)d_in[4];
    const float* Wk   = (const float*)d_in[5];
    const float* bk   = (const float*)d_in[6];
    const float* Wv   = (const float*)d_in[7];
    const float* bv   = (const float*)d_in[8];

    prep_weights<<<dim3(C * C / 1024, 3), 256>>>(Wq, Wk, Wv);

    cudaFuncSetAttribute(fused_kernel, cudaFuncAttributeMaxDynamicSharedMemorySize, SMEM_BYTES);
    fused_kernel<<<NV, 256, SMEM_BYTES>>>(nmat, s, v, bq, bk, bv, (float*)d_out);
}

// round 9
// speedup vs baseline: 1.5974x; 1.5974x over previous
#include <cuda_runtime.h>
#include <cstdint>
#include <mma.h>
#include <math.h>

using namespace nvcuda;

namespace {
constexpr int NV = 512;   // nodes
constexpr int C  = 256;   // channels
constexpr int MT = 64;    // j-tile rows
constexpr int LDA = 260;  // padded A leading dim (floats); stride 1040B -> 4-bank row shift
constexpr int NWARP = 16;
constexpr int THREADS = 512;

// smem layout (floats)
constexpr int SM_A   = 0;                  // [MT][LDA]  = 16640
constexpr int SM_Q   = SM_A + MT * LDA;    // [MT][C]    = 16384
constexpr int SM_VE  = SM_Q + MT * C;      // [MT][C]    = 16384
constexpr int SM_N   = SM_VE + MT * C;     // [C]
constexpr int SM_BK  = SM_N + C;           // [C]
constexpr int SM_SC  = SM_BK + C;          // [MT]
constexpr int SM_P   = SM_SC + MT;         // [MT]
constexpr int SM_HR  = SM_P + MT;          // [THREADS] half-combine
constexpr int SM_RED = SM_HR + THREADS;    // [NWARP]
constexpr int SMEM_FLOATS = SM_RED + NWARP;
constexpr int SMEM_BYTES  = SMEM_FLOATS * 4;   // ~202.5 KB
}

// pre-rounded tf32 weights: [Wq | Wk | Wv]
__device__ float g_wt[3 * C * C];

__device__ __forceinline__ float to_tf32(float x) {
    float y; asm("cvt.rna.tf32.f32 %0, %1;" : "=f"(y) : "f"(x)); return y;
}

__global__ __launch_bounds__(256) void prep_weights(
    const float* __restrict__ Wq, const float* __restrict__ Wk, const float* __restrict__ Wv)
{
    const int idx = (blockIdx.x * 256 + threadIdx.x) * 4;
    const float* src = (blockIdx.y == 0) ? Wq : (blockIdx.y == 1 ? Wk : Wv);
    float4 t = *reinterpret_cast<const float4*>(src + idx);
    t.x = to_tf32(t.x); t.y = to_tf32(t.y); t.z = to_tf32(t.z); t.w = to_tf32(t.w);
    *reinterpret_cast<float4*>(g_wt + (size_t)blockIdx.y * C * C + idx) = t;
}

struct Acc { wmma::fragment<wmma::accumulator, 16, 16, 8, float> a[4]; };

// (64x256 tf32 A-tile in smem) @ W^T. Warp stripe: output cols [wid*16, wid*16+16).
// B double-buffered from global; k-loop unroll 2 ONLY (full unroll => LDG hoist => spill).
__device__ __forceinline__ void gemm16(Acc& f, const float* sA,
                                       const float* __restrict__ W, int wid) {
    wmma::fragment<wmma::matrix_a, 16, 16, 8, wmma::precision::tf32, wmma::row_major> af[4];
    wmma::fragment<wmma::matrix_b, 16, 16, 8, wmma::precision::tf32, wmma::col_major> bf[2];
#pragma unroll
    for (int m = 0; m < 4; m++) wmma::fill_fragment(f.a[m], 0.0f);

    const float* Wb = W + (size_t)(wid * 16) * C;   // col-major view, ld = C
    wmma::load_matrix_sync(bf[0], Wb, C);
#pragma unroll 2
    for (int k = 0; k < C; k += 8) {
        const int cur = (k >> 3) & 1;
        if (k + 8 < C) wmma::load_matrix_sync(bf[cur ^ 1], Wb + k + 8, C);
#pragma unroll
        for (int m = 0; m < 4; m++)
            wmma::load_matrix_sync(af[m], sA + m * 16 * LDA + k, LDA);
#pragma unroll
        for (int m = 0; m < 4; m++)
            wmma::mma_sync(f.a[m], af[m], bf[cur], f.a[m]);
    }
}

__device__ __forceinline__ void frag_store(Acc& f, float* dst, int ldm, int wid) {
#pragma unroll
    for (int m = 0; m < 4; m++)
        wmma::store_matrix_sync(dst + m * 16 * ldm + wid * 16, f.a[m], ldm, wmma::mem_row_major);
}

__global__ __launch_bounds__(THREADS, 1) void fused_kernel(
    const float* __restrict__ nmat, const float* __restrict__ s, const float* __restrict__ v,
    const float* __restrict__ bq, const float* __restrict__ bk, const float* __restrict__ bv,
    float* __restrict__ out)
{
    extern __shared__ float sm[];
    float* sA  = sm + SM_A;
    float* sQ  = sm + SM_Q;
    float* sVe = sm + SM_VE;
    float* sn  = sm + SM_N;
    float* sbk = sm + SM_BK;
    float* ssc = sm + SM_SC;
    float* sp  = sm + SM_P;
    float* shr = sm + SM_HR;
    float* red = sm + SM_RED;

    const int i    = blockIdx.x;
    const int tid  = threadIdx.x;
    const int wid  = tid >> 5;
    const int lane = tid & 31;
    const int ch   = tid & 255;   // owned channel for epilogues
    const int half = tid >> 8;    // j-half: rows [half*32, half*32+32)

    if (tid < C) { sn[tid] = nmat[(size_t)i * C + tid]; sbk[tid] = bk[tid]; }
    const float bq_r = bq[ch], bv_r = bv[ch];
    __syncthreads();

    float m_run = -1e30f, l_run = 0.0f, xacc = 0.0f;

    for (int jt = 0; jt < NV / MT; jt++) {
        const int j0 = jt * MT;
        __syncthreads();   // prev-iter smem readers done

        // build A[j][c] = tf32(n_i[c]*n_j[c]*s[i,j0+j,c]); 512 thr x 8 float4
#pragma unroll
        for (int it = 0; it < MT * (C / 4) / THREADS; it++) {
            const int idx = it * THREADS + tid;
            const int j  = idx >> 6;
            const int c4 = (idx & 63) * 4;
            const float4 n4  = *reinterpret_cast<const float4*>(nmat + (size_t)(j0 + j) * C + c4);
            const float4 s4  = *reinterpret_cast<const float4*>(s + ((size_t)i * NV + j0 + j) * C + c4);
            const float4 sn4 = *reinterpret_cast<const float4*>(sn + c4);
            float4 r;
            r.x = to_tf32(sn4.x * n4.x * s4.x);
            r.y = to_tf32(sn4.y * n4.y * s4.y);
            r.z = to_tf32(sn4.z * n4.z * s4.z);
            r.w = to_tf32(sn4.w * n4.w * s4.w);
            *reinterpret_cast<float4*>(sA + j * LDA + c4) = r;
        }
        __syncthreads();

        Acc f;
        gemm16(f, sA, g_wt,             wid); frag_store(f, sQ,  C, wid);  // Q
        gemm16(f, sA, g_wt + 2 * C * C, wid); frag_store(f, sVe, C, wid);  // V
        gemm16(f, sA, g_wt + 1 * C * C, wid);                              // K (regs)
        __syncthreads();                      // all warps done reading sA
        frag_store(f, sA, LDA, wid);          // Gk overwrites A

        // fold bq + v^2 into q~: thread owns (channel ch, rows half*32..+32)
        {
            const float* vrow = v + ((size_t)i * NV + j0 + half * 32) * C + ch;
            float* q = sQ + (half * 32) * C + ch;
#pragma unroll 4
            for (int jj = 0; jj < 32; jj++) {
                const float vv = vrow[(size_t)jj * C];
                q[jj * C] = (q[jj * C] + bq_r) * vv * vv;
            }
        }
        __syncthreads();                      // Gk + q~ visible

        // scores: 16 warps x 4 rows
#pragma unroll
        for (int r = 0; r < MT / NWARP; r++) {
            const int j = wid * (MT / NWARP) + r;
            float p = 0.0f;
#pragma unroll 4
            for (int d = lane; d < C; d += 32)
                p += sQ[j * C + d] * (sA[j * LDA + d] + sbk[d]);
#pragma unroll
            for (int o = 16; o > 0; o >>= 1) p += __shfl_xor_sync(0xffffffffu, p, o);
            if (lane == 0) ssc[j] = p * 0.0625f;   // 1/sqrt(256)
        }
        __syncthreads();

        // online softmax (replicated scalar math)
        float tm = -1e30f;
#pragma unroll 8
        for (int j = 0; j < MT; j++) tm = fmaxf(tm, ssc[j]);
        const float m_new = fmaxf(m_run, tm);
        const float scl = __expf(m_run - m_new);
        xacc *= scl; l_run *= scl;
        if (tid < MT) sp[tid] = __expf(ssc[tid] - m_new);
        __syncthreads();
        float ls = 0.0f;
#pragma unroll 8
        for (int j = 0; j < MT; j++) ls += sp[j];
        l_run += ls;
        m_run = m_new;

        // V accumulate over owned rows
        {
            const float* vrow = v + ((size_t)i * NV + j0 + half * 32) * C + ch;
            const float* ve = sVe + (half * 32) * C + ch;
            const float* pp = sp + half * 32;
#pragma unroll 4
            for (int jj = 0; jj < 32; jj++)
                xacc += pp[jj] * (ve[jj * C] + bv_r) * vrow[(size_t)jj * C];
        }
    }

    // combine halves, residual, L2-normalize
    __syncthreads();
    shr[half * 256 + ch] = xacc;
    __syncthreads();
    float x = 0.0f;
    if (tid < C) x = (shr[tid] + shr[256 + tid]) / l_run + sn[tid];
    float sq = (tid < C) ? x * x : 0.0f;
#pragma unroll
    for (int o = 16; o > 0; o >>= 1) sq += __shfl_xor_sync(0xffffffffu, sq, o);
    if (lane == 0) red[wid] = sq;
    __syncthreads();
    float tot = 0.0f;
#pragma unroll
    for (int w = 0; w < NWARP; w++) tot += red[w];
    if (tid < C) out[(size_t)i * C + tid] = x * rsqrtf(tot);
}

extern "C" void kernel_launch(void* const* d_in, const int* in_sizes, int n_in,
                              void* d_out, int out_size) {
    const float* nmat = (const float*)d_in[0];
    const float* s    = (const float*)d_in[1];
    const float* v    = (const float*)d_in[2];
    const float* Wq   = (const float*)d_in[3];
    const float* bq   = (const float*)d_in[4];
    const float* Wk   = (const float*)d_in[5];
    const float* bk   = (const float*)d_in[6];
    const float* Wv   = (const float*)d_in[7];
    const float* bv   = (const float*)d_in[8];

    prep_weights<<<dim3(C * C / 1024, 3), 256>>>(Wq, Wk, Wv);

    cudaFuncSetAttribute(fused_kernel, cudaFuncAttributeMaxDynamicSharedMemorySize, SMEM_BYTES);
    fused_kernel<<<NV, THREADS, SMEM_BYTES>>>(nmat, s, v, bq, bk, bv, (float*)d_out);
}

// round 10
// speedup vs baseline: 2.5514x; 1.5972x over previous
#include <cuda_runtime.h>
#include <cstdint>
#include <math.h>

namespace {
constexpr int NV = 512;
constexpr int C  = 256;
constexpr int MT = 64;        // j-rows per tile
constexpr int LDA = 260;      // padded smem stride (floats): conflict-free frag loads
constexpr int LDV = 260;
constexpr int NWARP = 16;
constexpr int THREADS = 512;

// smem layout (floats)
constexpr int SM_A   = 0;                  // [MT][LDA] tf32 A-tile
constexpr int SM_V   = SM_A + MT * LDA;    // [MT][LDV] v-tile (fp32)
constexpr int SM_N   = SM_V + MT * LDV;    // [C]
constexpr int SM_BQ  = SM_N + C;           // [C]
constexpr int SM_BK  = SM_BQ + C;          // [C]
constexpr int SM_BV  = SM_BK + C;          // [C]
constexpr int SM_STG = SM_BV + C;          // [64][17] score partials per warp
constexpr int SM_SC  = SM_STG + 64 * 17;   // [64] scores
constexpr int SM_P   = SM_SC + 64;         // [64] exp probs
constexpr int SM_SX  = SM_P + 64;          // [C] final x partials
constexpr int SM_RED = SM_SX + C;          // [NWARP]
constexpr int SMEM_FLOATS = SM_RED + NWARP;
constexpr int SMEM_BYTES  = SMEM_FLOATS * 4;   // ~146 KB
}

// pre-rounded tf32 weights: [Wq | Wk | Wv], row-major [d][c]
__device__ float g_wt[3 * C * C];

__device__ __forceinline__ float to_tf32(float x) {
    float y; asm("cvt.rna.tf32.f32 %0, %1;" : "=f"(y) : "f"(x)); return y;
}

__global__ __launch_bounds__(256) void prep_weights(
    const float* __restrict__ Wq, const float* __restrict__ Wk, const float* __restrict__ Wv)
{
    const int idx = (blockIdx.x * 256 + threadIdx.x) * 4;
    const float* src = (blockIdx.y == 0) ? Wq : (blockIdx.y == 1 ? Wk : Wv);
    float4 t = *reinterpret_cast<const float4*>(src + idx);
    t.x = to_tf32(t.x); t.y = to_tf32(t.y); t.z = to_tf32(t.z); t.w = to_tf32(t.w);
    *reinterpret_cast<float4*>(g_wt + (size_t)blockIdx.y * C * C + idx) = t;
}

// D += A*B : m16n8k8 tf32. A row-major (4 regs), B col-major (2 regs), C f32 (4 regs).
__device__ __forceinline__ void mma8(float c[4], const uint32_t a[4], const uint32_t b[2]) {
    asm volatile(
        "mma.sync.aligned.m16n8k8.row.col.f32.tf32.tf32.f32 "
        "{%0,%1,%2,%3}, {%4,%5,%6,%7}, {%8,%9}, {%0,%1,%2,%3};"
        : "+f"(c[0]), "+f"(c[1]), "+f"(c[2]), "+f"(c[3])
        : "r"(a[0]), "r"(a[1]), "r"(a[2]), "r"(a[3]), "r"(b[0]), "r"(b[1]));
}

// B fragment (k8n8, col-major) for weight W at (n-block base n0, k-chunk kc).
// b0: (k=lane&3,  n=lane>>2) ; b1: (k=lane&3+4, same n). W element (n,k) at W[n*C+k].
__device__ __forceinline__ void load_b(uint32_t b[2], const float* __restrict__ W,
                                       int n0, int kc, int qid, int qlane) {
    const float* p = W + (size_t)(n0 + qid) * C + kc * 8 + qlane;
    b[0] = __float_as_uint(__ldg(p));
    b[1] = __float_as_uint(__ldg(p + 4));
}

// A fragment (m16k8, row-major) from smem tile at m-block mb, k-chunk kc.
__device__ __forceinline__ void load_a(uint32_t a[4], const uint32_t* sAu,
                                       int mb, int kc, int qid, int qlane) {
    const uint32_t* p = sAu + (mb * 16 + qid) * LDA + kc * 8 + qlane;
    a[0] = p[0];
    a[1] = p[8 * LDA];
    a[2] = p[4];
    a[3] = p[8 * LDA + 4];
}

__global__ __launch_bounds__(THREADS, 1) void fused_kernel(
    const float* __restrict__ nmat, const float* __restrict__ s, const float* __restrict__ v,
    const float* __restrict__ bq, const float* __restrict__ bk, const float* __restrict__ bv,
    float* __restrict__ out)
{
    extern __shared__ float sm[];
    float* sA  = sm + SM_A;
    float* sv  = sm + SM_V;
    float* sn  = sm + SM_N;
    float* sbq = sm + SM_BQ;
    float* sbk = sm + SM_BK;
    float* sbv = sm + SM_BV;
    float* stg = sm + SM_STG;
    float* ssc = sm + SM_SC;
    float* sp  = sm + SM_P;
    float* sx  = sm + SM_SX;
    float* red = sm + SM_RED;
    const uint32_t* sAu = reinterpret_cast<const uint32_t*>(sA);

    const int i     = blockIdx.x;
    const int tid   = threadIdx.x;
    const int wid   = tid >> 5;
    const int lane  = tid & 31;
    const int qid   = lane >> 2;      // group id (row within fragment)
    const int qlane = lane & 3;       // thread in group
    const int wc0   = wid * 16;       // warp's first output column

    if (tid < C) {
        sn[tid]  = nmat[(size_t)i * C + tid];
        sbq[tid] = bq[tid];
        sbk[tid] = bk[tid];
        sbv[tid] = bv[tid];
    }

    float m_run = -1e30f, l_run = 0.0f;
    float xr[4] = {0.f, 0.f, 0.f, 0.f};   // col accumulators: (nb, parity)

    for (int jt = 0; jt < NV / MT; jt++) {
        const int j0 = jt * MT;
        __syncthreads();   // prior-tile readers of sA/sv done (also covers init stores)

        // build A[j][c] = tf32(n_i[c]*n_j[c]*s[..]) and v-tile
#pragma unroll
        for (int it = 0; it < MT * (C / 4) / THREADS; it++) {
            const int idx = it * THREADS + tid;
            const int j  = idx >> 6;
            const int c4 = (idx & 63) * 4;
            const float4 n4  = *reinterpret_cast<const float4*>(nmat + (size_t)(j0 + j) * C + c4);
            const float4 s4  = *reinterpret_cast<const float4*>(s + ((size_t)i * NV + j0 + j) * C + c4);
            const float4 sn4 = *reinterpret_cast<const float4*>(sn + c4);
            float4 r;
            r.x = to_tf32(sn4.x * n4.x * s4.x);
            r.y = to_tf32(sn4.y * n4.y * s4.y);
            r.z = to_tf32(sn4.z * n4.z * s4.z);
            r.w = to_tf32(sn4.w * n4.w * s4.w);
            *reinterpret_cast<float4*>(sA + j * LDA + c4) = r;
            const float4 v4 = *reinterpret_cast<const float4*>(v + ((size_t)i * NV + j0 + j) * C + c4);
            *reinterpret_cast<float4*>(sv + j * LDV + c4) = v4;
        }
        __syncthreads();

        // ── fused Q+K GEMM, all in registers
        float qacc[4][2][4], kacc[4][2][4];
#pragma unroll
        for (int mb = 0; mb < 4; mb++)
#pragma unroll
            for (int nb = 0; nb < 2; nb++)
#pragma unroll
                for (int e = 0; e < 4; e++) { qacc[mb][nb][e] = 0.f; kacc[mb][nb][e] = 0.f; }
        {
            uint32_t bqf[2][2][2], bkf[2][2][2];   // [buf][nb][reg]
            load_b(bqf[0][0], g_wt,             wc0,     0, qid, qlane);
            load_b(bqf[0][1], g_wt,             wc0 + 8, 0, qid, qlane);
            load_b(bkf[0][0], g_wt + 1 * C * C, wc0,     0, qid, qlane);
            load_b(bkf[0][1], g_wt + 1 * C * C, wc0 + 8, 0, qid, qlane);
#pragma unroll 2
            for (int kc = 0; kc < 32; kc++) {
                const int cur = kc & 1;
                if (kc + 1 < 32) {
                    load_b(bqf[cur ^ 1][0], g_wt,             wc0,     kc + 1, qid, qlane);
                    load_b(bqf[cur ^ 1][1], g_wt,             wc0 + 8, kc + 1, qid, qlane);
                    load_b(bkf[cur ^ 1][0], g_wt + 1 * C * C, wc0,     kc + 1, qid, qlane);
                    load_b(bkf[cur ^ 1][1], g_wt + 1 * C * C, wc0 + 8, kc + 1, qid, qlane);
                }
#pragma unroll
                for (int mb = 0; mb < 4; mb++) {
                    uint32_t a[4];
                    load_a(a, sAu, mb, kc, qid, qlane);
                    mma8(qacc[mb][0], a, bqf[cur][0]);
                    mma8(qacc[mb][1], a, bqf[cur][1]);
                    mma8(kacc[mb][0], a, bkf[cur][0]);
                    mma8(kacc[mb][1], a, bkf[cur][1]);
                }
            }
        }

        // ── scores in-register: partial per (mb, rowhalf)
        {
            float pr[8];
#pragma unroll
            for (int z = 0; z < 8; z++) pr[z] = 0.f;
#pragma unroll
            for (int nb = 0; nb < 2; nb++) {
                const int c0 = wc0 + nb * 8 + 2 * qlane;
                const float bq0 = sbq[c0], bq1 = sbq[c0 + 1];
                const float bk0 = sbk[c0], bk1 = sbk[c0 + 1];
#pragma unroll
                for (int mb = 0; mb < 4; mb++) {
                    const int r0 = mb * 16 + qid;
                    const float v00 = sv[r0 * LDV + c0],       v01 = sv[r0 * LDV + c0 + 1];
                    const float v10 = sv[(r0 + 8) * LDV + c0], v11 = sv[(r0 + 8) * LDV + c0 + 1];
                    pr[mb * 2 + 0] += (qacc[mb][nb][0] + bq0) * (kacc[mb][nb][0] + bk0) * v00 * v00
                                    + (qacc[mb][nb][1] + bq1) * (kacc[mb][nb][1] + bk1) * v01 * v01;
                    pr[mb * 2 + 1] += (qacc[mb][nb][2] + bq0) * (kacc[mb][nb][2] + bk0) * v10 * v10
                                    + (qacc[mb][nb][3] + bq1) * (kacc[mb][nb][3] + bk1) * v11 * v11;
                }
            }
#pragma unroll
            for (int z = 0; z < 8; z++) {
                pr[z] += __shfl_xor_sync(0xffffffffu, pr[z], 1);
                pr[z] += __shfl_xor_sync(0xffffffffu, pr[z], 2);
            }
            if (qlane == 0) {
#pragma unroll
                for (int mb = 0; mb < 4; mb++) {
                    stg[(mb * 16 + qid) * 17 + wid]     = pr[mb * 2 + 0];
                    stg[(mb * 16 + qid + 8) * 17 + wid] = pr[mb * 2 + 1];
                }
            }
        }
        __syncthreads();

        // row-reduce 16 warp partials -> scores
        {
            const int row = tid >> 3, k8 = tid & 7;
            float ssum = stg[row * 17 + k8] + stg[row * 17 + 8 + k8];
            ssum += __shfl_xor_sync(0xffffffffu, ssum, 1);
            ssum += __shfl_xor_sync(0xffffffffu, ssum, 2);
            ssum += __shfl_xor_sync(0xffffffffu, ssum, 4);
            if (k8 == 0) ssc[row] = ssum * 0.0625f;   // 1/sqrt(256)
        }
        __syncthreads();

        // online softmax (replicated)
        {
            float tm = -1e30f;
#pragma unroll 8
            for (int j = 0; j < MT; j++) tm = fmaxf(tm, ssc[j]);
            const float m_new = fmaxf(m_run, tm);
            const float scl = __expf(m_run - m_new);
            l_run *= scl;
#pragma unroll
            for (int z = 0; z < 4; z++) xr[z] *= scl;
            if (tid < MT) sp[tid] = __expf(ssc[tid] - m_new);
            __syncthreads();
            float ls = 0.0f;
#pragma unroll 8
            for (int j = 0; j < MT; j++) ls += sp[j];
            l_run += ls;
            m_run = m_new;
        }

        // ── V GEMM (same A, acc regs reused)
        float vacc[4][2][4];
#pragma unroll
        for (int mb = 0; mb < 4; mb++)
#pragma unroll
            for (int nb = 0; nb < 2; nb++)
#pragma unroll
                for (int e = 0; e < 4; e++) vacc[mb][nb][e] = 0.f;
        {
            uint32_t bvf[2][2][2];
            load_b(bvf[0][0], g_wt + 2 * C * C, wc0,     0, qid, qlane);
            load_b(bvf[0][1], g_wt + 2 * C * C, wc0 + 8, 0, qid, qlane);
#pragma unroll 2
            for (int kc = 0; kc < 32; kc++) {
                const int cur = kc & 1;
                if (kc + 1 < 32) {
                    load_b(bvf[cur ^ 1][0], g_wt + 2 * C * C, wc0,     kc + 1, qid, qlane);
                    load_b(bvf[cur ^ 1][1], g_wt + 2 * C * C, wc0 + 8, kc + 1, qid, qlane);
                }
#pragma unroll
                for (int mb = 0; mb < 4; mb++) {
                    uint32_t a[4];
                    load_a(a, sAu, mb, kc, qid, qlane);
                    mma8(vacc[mb][0], a, bvf[cur][0]);
                    mma8(vacc[mb][1], a, bvf[cur][1]);
                }
            }
        }

        // ── V epilogue in-register: xr[nb*2+par] += sum_rows p * (gv+bv) * v
        {
#pragma unroll
            for (int nb = 0; nb < 2; nb++) {
                const int c0 = wc0 + nb * 8 + 2 * qlane;
                const float bv0 = sbv[c0], bv1 = sbv[c0 + 1];
                float pc0 = 0.f, pc1 = 0.f;
#pragma unroll
                for (int mb = 0; mb < 4; mb++) {
                    const int r0 = mb * 16 + qid;
                    const float p0 = sp[r0], p1 = sp[r0 + 8];
                    pc0 += p0 * (vacc[mb][nb][0] + bv0) * sv[r0 * LDV + c0]
                         + p1 * (vacc[mb][nb][2] + bv0) * sv[(r0 + 8) * LDV + c0];
                    pc1 += p0 * (vacc[mb][nb][1] + bv1) * sv[r0 * LDV + c0 + 1]
                         + p1 * (vacc[mb][nb][3] + bv1) * sv[(r0 + 8) * LDV + c0 + 1];
                }
                pc0 += __shfl_xor_sync(0xffffffffu, pc0, 4);
                pc0 += __shfl_xor_sync(0xffffffffu, pc0, 8);
                pc0 += __shfl_xor_sync(0xffffffffu, pc0, 16);
                pc1 += __shfl_xor_sync(0xffffffffu, pc1, 4);
                pc1 += __shfl_xor_sync(0xffffffffu, pc1, 8);
                pc1 += __shfl_xor_sync(0xffffffffu, pc1, 16);
                xr[nb * 2 + 0] += pc0;
                xr[nb * 2 + 1] += pc1;
            }
        }
    }

    // publish per-warp column results (each col written by exactly one lane)
    if (qid == 0) {
#pragma unroll
        for (int nb = 0; nb < 2; nb++) {
            sx[wc0 + nb * 8 + 2 * qlane]     = xr[nb * 2 + 0];
            sx[wc0 + nb * 8 + 2 * qlane + 1] = xr[nb * 2 + 1];
        }
    }
    __syncthreads();

    // residual + L2 normalize (first 256 threads own channels)
    float x = 0.0f;
    if (tid < C) x = sx[tid] / l_run + sn[tid];
    float sq = (tid < C) ? x * x : 0.0f;
#pragma unroll
    for (int o = 16; o > 0; o >>= 1) sq += __shfl_xor_sync(0xffffffffu, sq, o);
    if (lane == 0) red[wid] = sq;
    __syncthreads();
    float tot = 0.0f;
#pragma unroll
    for (int w = 0; w < NWARP; w++) tot += red[w];
    if (tid < C) out[(size_t)i * C + tid] = x * rsqrtf(tot);
}

extern "C" void kernel_launch(void* const* d_in, const int* in_sizes, int n_in,
                              void* d_out, int out_size) {
    const float* nmat = (const float*)d_in[0];
    const float* s    = (const float*)d_in[1];
    const float* v    = (const float*)d_in[2];
    const float* Wq   = (const float*)d_in[3];
    const float* bq   = (const float*)d_in[4];
    const float* Wk   = (const float*)d_in[5];
    const float* bk   = (const float*)d_in[6];
    const float* Wv   = (const float*)d_in[7];
    const float* bv   = (const float*)d_in[8];

    prep_weights<<<dim3(C * C / 1024, 3), 256>>>(Wq, Wk, Wv);

    cudaFuncSetAttribute(fused_kernel, cudaFuncAttributeMaxDynamicSharedMemorySize, SMEM_BYTES);
    fused_kernel<<<NV, THREADS, SMEM_BYTES>>>(nmat, s, v, bq, bk, bv, (float*)d_out);
}

// round 11
// speedup vs baseline: 3.7775x; 1.4806x over previous
#include <cuda_runtime.h>
#include <cstdint>
#include <math.h>

namespace {
constexpr int NV = 512;
constexpr int C  = 256;
constexpr int MT = 64;        // j-rows per tile
constexpr int LDA = 260;      // padded smem stride (floats): rows 16B apart mod 128
constexpr int LDV = 260;
constexpr int NWARP = 16;
constexpr int THREADS = 512;

// smem layout (floats)
constexpr int SM_A   = 0;                  // [MT][LDA] tf32 A-tile
constexpr int SM_V   = SM_A + MT * LDA;    // [MT][LDV] v-tile (fp32)
constexpr int SM_N   = SM_V + MT * LDV;    // [C]
constexpr int SM_BQ  = SM_N + C;           // [C]
constexpr int SM_BK  = SM_BQ + C;          // [C]
constexpr int SM_BV  = SM_BK + C;          // [C]
constexpr int SM_STG = SM_BV + C;          // [64][17] score partials per warp
constexpr int SM_SC  = SM_STG + 64 * 17;   // [64] scores
constexpr int SM_P   = SM_SC + 64;         // [64] exp probs
constexpr int SM_SX  = SM_P + 64;          // [C] final x partials
constexpr int SM_RED = SM_SX + C;          // [NWARP]
constexpr int SMEM_FLOATS = SM_RED + NWARP;
constexpr int SMEM_BYTES  = SMEM_FLOATS * 4;   // ~146 KB
}

// pre-rounded tf32 weights, k-pair-permuted: within each 8-col k-block of a row,
// stored order is c0,c0+4,c0+1,c0+5,c0+2,c0+6,c0+3,c0+7  -> one LDG.64 per B frag.
__device__ float g_wt[3 * C * C];

__device__ __forceinline__ float to_tf32(float x) {
    float y; asm("cvt.rna.tf32.f32 %0, %1;" : "=f"(y) : "f"(x)); return y;
}
__device__ __forceinline__ uint32_t smem_u32(const void* p) {
    uint32_t a;
    asm("{ .reg .u64 t; cvta.to.shared.u64 t, %1; cvt.u32.u64 %0, t; }" : "=r"(a) : "l"(p));
    return a;
}

// One thread handles one 8-col k-block of one weight row: read 2xfloat4, write permuted.
__global__ __launch_bounds__(256) void prep_weights(
    const float* __restrict__ Wq, const float* __restrict__ Wk, const float* __restrict__ Wv)
{
    const int id  = blockIdx.x * 256 + threadIdx.x;     // [0, 8192) block id
    const int row = id >> 5, blk = id & 31;
    const float* src = (blockIdx.y == 0) ? Wq : (blockIdx.y == 1 ? Wk : Wv);
    const float* p = src + (size_t)row * C + blk * 8;
    float4 lo = *reinterpret_cast<const float4*>(p);
    float4 hi = *reinterpret_cast<const float4*>(p + 4);
    float4 o0, o1;
    o0.x = to_tf32(lo.x); o0.y = to_tf32(hi.x); o0.z = to_tf32(lo.y); o0.w = to_tf32(hi.y);
    o1.x = to_tf32(lo.z); o1.y = to_tf32(hi.z); o1.z = to_tf32(lo.w); o1.w = to_tf32(hi.w);
    float* dst = g_wt + (size_t)blockIdx.y * C * C + (size_t)row * C + blk * 8;
    *reinterpret_cast<float4*>(dst)     = o0;
    *reinterpret_cast<float4*>(dst + 4) = o1;
}

// D += A*B : m16n8k8 tf32.
__device__ __forceinline__ void mma8(float c[4], const uint32_t a[4], const uint32_t b[2]) {
    asm volatile(
        "mma.sync.aligned.m16n8k8.row.col.f32.tf32.tf32.f32 "
        "{%0,%1,%2,%3}, {%4,%5,%6,%7}, {%8,%9}, {%0,%1,%2,%3};"
        : "+f"(c[0]), "+f"(c[1]), "+f"(c[2]), "+f"(c[3])
        : "r"(a[0]), "r"(a[1]), "r"(a[2]), "r"(a[3]), "r"(b[0]), "r"(b[1]));
}

// A fragment via ldmatrix: 4 regs in one LDSM.x4 (raw 32-bit moves through b16 path).
__device__ __forceinline__ void ldsm_x4(uint32_t a[4], uint32_t addr) {
    asm volatile("ldmatrix.sync.aligned.m8n8.x4.shared.b16 {%0,%1,%2,%3}, [%4];"
                 : "=r"(a[0]), "=r"(a[1]), "=r"(a[2]), "=r"(a[3]) : "r"(addr));
}

// B fragment from permuted weights: one 64-bit load.
__device__ __forceinline__ void load_b(uint32_t b[2], const float* __restrict__ W,
                                       int n0, int kc, int qid, int qlane) {
    const float2 t = *reinterpret_cast<const float2*>(
        W + (size_t)(n0 + qid) * C + kc * 8 + qlane * 2);
    b[0] = __float_as_uint(t.x);
    b[1] = __float_as_uint(t.y);
}

__global__ __launch_bounds__(THREADS, 1) void fused_kernel(
    const float* __restrict__ nmat, const float* __restrict__ s, const float* __restrict__ v,
    const float* __restrict__ bq, const float* __restrict__ bk, const float* __restrict__ bv,
    float* __restrict__ out)
{
    extern __shared__ float sm[];
    float* sA  = sm + SM_A;
    float* sv  = sm + SM_V;
    float* sn  = sm + SM_N;
    float* sbq = sm + SM_BQ;
    float* sbk = sm + SM_BK;
    float* sbv = sm + SM_BV;
    float* stg = sm + SM_STG;
    float* ssc = sm + SM_SC;
    float* sp  = sm + SM_P;
    float* sx  = sm + SM_SX;
    float* red = sm + SM_RED;

    const int i     = blockIdx.x;
    const int tid   = threadIdx.x;
    const int wid   = tid >> 5;
    const int lane  = tid & 31;
    const int qid   = lane >> 2;
    const int qlane = lane & 3;
    const int wc0   = wid * 16;       // warp's first output column

    // per-lane ldmatrix base: row = lane&15, col offset = (lane>>4)*4
    const uint32_t aBase = smem_u32(sA)
        + (uint32_t)(((lane & 15) * LDA + ((lane >> 4) << 2)) * 4);

    if (tid < C) {
        sn[tid]  = nmat[(size_t)i * C + tid];
        sbq[tid] = bq[tid];
        sbk[tid] = bk[tid];
        sbv[tid] = bv[tid];
    }

    float m_run = -1e30f, l_run = 0.0f;
    float xr[4] = {0.f, 0.f, 0.f, 0.f};

    for (int jt = 0; jt < NV / MT; jt++) {
        const int j0 = jt * MT;
        __syncthreads();   // prior-tile readers of sA/sv done (also covers init stores)

        // build A[j][c] = tf32(n_i[c]*n_j[c]*s[..]) and v-tile
#pragma unroll
        for (int it = 0; it < MT * (C / 4) / THREADS; it++) {
            const int idx = it * THREADS + tid;
            const int j  = idx >> 6;
            const int c4 = (idx & 63) * 4;
            const float4 n4  = *reinterpret_cast<const float4*>(nmat + (size_t)(j0 + j) * C + c4);
            const float4 s4  = *reinterpret_cast<const float4*>(s + ((size_t)i * NV + j0 + j) * C + c4);
            const float4 sn4 = *reinterpret_cast<const float4*>(sn + c4);
            float4 r;
            r.x = to_tf32(sn4.x * n4.x * s4.x);
            r.y = to_tf32(sn4.y * n4.y * s4.y);
            r.z = to_tf32(sn4.z * n4.z * s4.z);
            r.w = to_tf32(sn4.w * n4.w * s4.w);
            *reinterpret_cast<float4*>(sA + j * LDA + c4) = r;
            const float4 v4 = *reinterpret_cast<const float4*>(v + ((size_t)i * NV + j0 + j) * C + c4);
            *reinterpret_cast<float4*>(sv + j * LDV + c4) = v4;
        }
        __syncthreads();

        // ── fused Q+K GEMM, all in registers
        float qacc[4][2][4], kacc[4][2][4];
#pragma unroll
        for (int mb = 0; mb < 4; mb++)
#pragma unroll
            for (int nb = 0; nb < 2; nb++)
#pragma unroll
                for (int e = 0; e < 4; e++) { qacc[mb][nb][e] = 0.f; kacc[mb][nb][e] = 0.f; }
        {
            uint32_t bqf[2][2][2], bkf[2][2][2];   // [buf][nb][reg]
            load_b(bqf[0][0], g_wt,             wc0,     0, qid, qlane);
            load_b(bqf[0][1], g_wt,             wc0 + 8, 0, qid, qlane);
            load_b(bkf[0][0], g_wt + 1 * C * C, wc0,     0, qid, qlane);
            load_b(bkf[0][1], g_wt + 1 * C * C, wc0 + 8, 0, qid, qlane);
#pragma unroll 2
            for (int kc = 0; kc < 32; kc++) {
                const int cur = kc & 1;
                if (kc + 1 < 32) {
                    load_b(bqf[cur ^ 1][0], g_wt,             wc0,     kc + 1, qid, qlane);
                    load_b(bqf[cur ^ 1][1], g_wt,             wc0 + 8, kc + 1, qid, qlane);
                    load_b(bkf[cur ^ 1][0], g_wt + 1 * C * C, wc0,     kc + 1, qid, qlane);
                    load_b(bkf[cur ^ 1][1], g_wt + 1 * C * C, wc0 + 8, kc + 1, qid, qlane);
                }
#pragma unroll
                for (int mb = 0; mb < 4; mb++) {
                    uint32_t a[4];
                    ldsm_x4(a, aBase + (uint32_t)((mb * 16 * LDA + kc * 8) * 4));
                    mma8(qacc[mb][0], a, bqf[cur][0]);
                    mma8(qacc[mb][1], a, bqf[cur][1]);
                    mma8(kacc[mb][0], a, bkf[cur][0]);
                    mma8(kacc[mb][1], a, bkf[cur][1]);
                }
            }
        }

        // ── scores in-register
        {
            float pr[8];
#pragma unroll
            for (int z = 0; z < 8; z++) pr[z] = 0.f;
#pragma unroll
            for (int nb = 0; nb < 2; nb++) {
                const int c0 = wc0 + nb * 8 + 2 * qlane;
                const float bq0 = sbq[c0], bq1 = sbq[c0 + 1];
                const float bk0 = sbk[c0], bk1 = sbk[c0 + 1];
#pragma unroll
                for (int mb = 0; mb < 4; mb++) {
                    const int r0 = mb * 16 + qid;
                    const float2 va = *reinterpret_cast<const float2*>(sv + r0 * LDV + c0);
                    const float2 vb = *reinterpret_cast<const float2*>(sv + (r0 + 8) * LDV + c0);
                    pr[mb * 2 + 0] += (qacc[mb][nb][0] + bq0) * (kacc[mb][nb][0] + bk0) * va.x * va.x
                                    + (qacc[mb][nb][1] + bq1) * (kacc[mb][nb][1] + bk1) * va.y * va.y;
                    pr[mb * 2 + 1] += (qacc[mb][nb][2] + bq0) * (kacc[mb][nb][2] + bk0) * vb.x * vb.x
                                    + (qacc[mb][nb][3] + bq1) * (kacc[mb][nb][3] + bk1) * vb.y * vb.y;
                }
            }
#pragma unroll
            for (int z = 0; z < 8; z++) {
                pr[z] += __shfl_xor_sync(0xffffffffu, pr[z], 1);
                pr[z] += __shfl_xor_sync(0xffffffffu, pr[z], 2);
            }
            if (qlane == 0) {
#pragma unroll
                for (int mb = 0; mb < 4; mb++) {
                    stg[(mb * 16 + qid) * 17 + wid]     = pr[mb * 2 + 0];
                    stg[(mb * 16 + qid + 8) * 17 + wid] = pr[mb * 2 + 1];
                }
            }
        }
        __syncthreads();

        // row-reduce 16 warp partials -> scores
        {
            const int row = tid >> 3, k8 = tid & 7;
            float ssum = stg[row * 17 + k8] + stg[row * 17 + 8 + k8];
            ssum += __shfl_xor_sync(0xffffffffu, ssum, 1);
            ssum += __shfl_xor_sync(0xffffffffu, ssum, 2);
            ssum += __shfl_xor_sync(0xffffffffu, ssum, 4);
            if (k8 == 0) ssc[row] = ssum * 0.0625f;   // 1/sqrt(256)
        }
        __syncthreads();

        // online softmax (replicated)
        {
            float tm = -1e30f;
#pragma unroll 8
            for (int j = 0; j < MT; j++) tm = fmaxf(tm, ssc[j]);
            const float m_new = fmaxf(m_run, tm);
            const float scl = __expf(m_run - m_new);
            l_run *= scl;
#pragma unroll
            for (int z = 0; z < 4; z++) xr[z] *= scl;
            if (tid < MT) sp[tid] = __expf(ssc[tid] - m_new);
            __syncthreads();
            float ls = 0.0f;
#pragma unroll 8
            for (int j = 0; j < MT; j++) ls += sp[j];
            l_run += ls;
            m_run = m_new;
        }

        // ── V GEMM (same A tile)
        float vacc[4][2][4];
#pragma unroll
        for (int mb = 0; mb < 4; mb++)
#pragma unroll
            for (int nb = 0; nb < 2; nb++)
#pragma unroll
                for (int e = 0; e < 4; e++) vacc[mb][nb][e] = 0.f;
        {
            uint32_t bvf[2][2][2];
            load_b(bvf[0][0], g_wt + 2 * C * C, wc0,     0, qid, qlane);
            load_b(bvf[0][1], g_wt + 2 * C * C, wc0 + 8, 0, qid, qlane);
#pragma unroll 2
            for (int kc = 0; kc < 32; kc++) {
                const int cur = kc & 1;
                if (kc + 1 < 32) {
                    load_b(bvf[cur ^ 1][0], g_wt + 2 * C * C, wc0,     kc + 1, qid, qlane);
                    load_b(bvf[cur ^ 1][1], g_wt + 2 * C * C, wc0 + 8, kc + 1, qid, qlane);
                }
#pragma unroll
                for (int mb = 0; mb < 4; mb++) {
                    uint32_t a[4];
                    ldsm_x4(a, aBase + (uint32_t)((mb * 16 * LDA + kc * 8) * 4));
                    mma8(vacc[mb][0], a, bvf[cur][0]);
                    mma8(vacc[mb][1], a, bvf[cur][1]);
                }
            }
        }

        // ── V epilogue in-register
        {
#pragma unroll
            for (int nb = 0; nb < 2; nb++) {
                const int c0 = wc0 + nb * 8 + 2 * qlane;
                const float bv0 = sbv[c0], bv1 = sbv[c0 + 1];
                float pc0 = 0.f, pc1 = 0.f;
#pragma unroll
                for (int mb = 0; mb < 4; mb++) {
                    const int r0 = mb * 16 + qid;
                    const float p0 = sp[r0], p1 = sp[r0 + 8];
                    const float2 va = *reinterpret_cast<const float2*>(sv + r0 * LDV + c0);
                    const float2 vb = *reinterpret_cast<const float2*>(sv + (r0 + 8) * LDV + c0);
                    pc0 += p0 * (vacc[mb][nb][0] + bv0) * va.x
                         + p1 * (vacc[mb][nb][2] + bv0) * vb.x;
                    pc1 += p0 * (vacc[mb][nb][1] + bv1) * va.y
                         + p1 * (vacc[mb][nb][3] + bv1) * vb.y;
                }
                pc0 += __shfl_xor_sync(0xffffffffu, pc0, 4);
                pc0 += __shfl_xor_sync(0xffffffffu, pc0, 8);
                pc0 += __shfl_xor_sync(0xffffffffu, pc0, 16);
                pc1 += __shfl_xor_sync(0xffffffffu, pc1, 4);
                pc1 += __shfl_xor_sync(0xffffffffu, pc1, 8);
                pc1 += __shfl_xor_sync(0xffffffffu, pc1, 16);
                xr[nb * 2 + 0] += pc0;
                xr[nb * 2 + 1] += pc1;
            }
        }
    }

    // publish per-warp column results
    if (qid == 0) {
#pragma unroll
        for (int nb = 0; nb < 2; nb++) {
            sx[wc0 + nb * 8 + 2 * qlane]     = xr[nb * 2 + 0];
            sx[wc0 + nb * 8 + 2 * qlane + 1] = xr[nb * 2 + 1];
        }
    }
    __syncthreads();

    // residual + L2 normalize
    float x = 0.0f;
    if (tid < C) x = sx[tid] / l_run + sn[tid];
    float sq = (tid < C) ? x * x : 0.0f;
#pragma unroll
    for (int o = 16; o > 0; o >>= 1) sq += __shfl_xor_sync(0xffffffffu, sq, o);
    if (lane == 0) red[wid] = sq;
    __syncthreads();
    float tot = 0.0f;
#pragma unroll
    for (int w = 0; w < NWARP; w++) tot += red[w];
    if (tid < C) out[(size_t)i * C + tid] = x * rsqrtf(tot);
}

extern "C" void kernel_launch(void* const* d_in, const int* in_sizes, int n_in,
                              void* d_out, int out_size) {
    const float* nmat = (const float*)d_in[0];
    const float* s    = (const float*)d_in[1];
    const float* v    = (const float*)d_in[2];
    const float* Wq   = (const float*)d_in[3];
    const float* bq   = (const float*)d_in[4];
    const float* Wk   = (const float*)d_in[5];
    const float* bk   = (const float*)d_in[6];
    const float* Wv   = (const float*)d_in[7];
    const float* bv   = (const float*)d_in[8];

    prep_weights<<<dim3(32, 3), 256>>>(Wq, Wk, Wv);

    cudaFuncSetAttribute(fused_kernel, cudaFuncAttributeMaxDynamicSharedMemorySize, SMEM_BYTES);
    fused_kernel<<<NV, THREADS, SMEM_BYTES>>>(nmat, s, v, bq, bk, bv, (float*)d_out);
}

// round 13
// speedup vs baseline: 4.0681x; 1.0769x over previous
#include <cuda_runtime.h>
#include <cstdint>
#include <math.h>

namespace {
constexpr int NV = 512;
constexpr int C  = 256;
constexpr int MT = 64;        // j-rows per tile
constexpr int LDA = 260;      // padded smem stride (floats): rows 16B apart mod 128
constexpr int LDV = 260;
constexpr int NWARP = 16;
constexpr int THREADS = 512;

// smem layout (floats)
constexpr int SM_A   = 0;                  // [MT][LDA] tf32 A-tile
constexpr int SM_V   = SM_A + MT * LDA;    // [MT][LDV] v-tile (fp32)
constexpr int SM_N   = SM_V + MT * LDV;    // [C]
constexpr int SM_BQ  = SM_N + C;           // [C]
constexpr int SM_BK  = SM_BQ + C;          // [C]
constexpr int SM_BV  = SM_BK + C;          // [C]
constexpr int SM_STG = SM_BV + C;          // [64][17] score partials per warp
constexpr int SM_SC  = SM_STG + 64 * 17;   // [64] scores
constexpr int SM_P   = SM_SC + 64;         // [64] exp probs
constexpr int SM_SX  = SM_P + 64;          // [C] final x partials
constexpr int SM_RED = SM_SX + C;          // [NWARP]
constexpr int SMEM_FLOATS = SM_RED + NWARP;
constexpr int SMEM_BYTES  = SMEM_FLOATS * 4;   // ~146 KB
}

// pre-rounded tf32 weights, k-pair-permuted: within each 8-col k-block of a row,
// stored order c0,c0+4,c0+1,c0+5,c0+2,c0+6,c0+3,c0+7  -> one LDG.64 per B frag.
__device__ float g_wt[3 * C * C];

__device__ __forceinline__ float to_tf32(float x) {
    float y; asm("cvt.rna.tf32.f32 %0, %1;" : "=f"(y) : "f"(x)); return y;
}
__device__ __forceinline__ uint32_t smem_u32(const void* p) {
    uint32_t a;
    asm("{ .reg .u64 t; cvta.to.shared.u64 t, %1; cvt.u32.u64 %0, t; }" : "=r"(a) : "l"(p));
    return a;
}

__global__ __launch_bounds__(256) void prep_weights(
    const float* __restrict__ Wq, const float* __restrict__ Wk, const float* __restrict__ Wv)
{
    const int id  = blockIdx.x * 256 + threadIdx.x;
    const int row = id >> 5, blk = id & 31;
    const float* src = (blockIdx.y == 0) ? Wq : (blockIdx.y == 1 ? Wk : Wv);
    const float* p = src + (size_t)row * C + blk * 8;
    float4 lo = *reinterpret_cast<const float4*>(p);
    float4 hi = *reinterpret_cast<const float4*>(p + 4);
    float4 o0, o1;
    o0.x = to_tf32(lo.x); o0.y = to_tf32(hi.x); o0.z = to_tf32(lo.y); o0.w = to_tf32(hi.y);
    o1.x = to_tf32(lo.z); o1.y = to_tf32(hi.z); o1.z = to_tf32(lo.w); o1.w = to_tf32(hi.w);
    float* dst = g_wt + (size_t)blockIdx.y * C * C + (size_t)row * C + blk * 8;
    *reinterpret_cast<float4*>(dst)     = o0;
    *reinterpret_cast<float4*>(dst + 4) = o1;
}

// D += A*B : m16n8k8 tf32.
__device__ __forceinline__ void mma8(float c[4], const uint32_t a[4], const uint32_t b[2]) {
    asm volatile(
        "mma.sync.aligned.m16n8k8.row.col.f32.tf32.tf32.f32 "
        "{%0,%1,%2,%3}, {%4,%5,%6,%7}, {%8,%9}, {%0,%1,%2,%3};"
        : "+f"(c[0]), "+f"(c[1]), "+f"(c[2]), "+f"(c[3])
        : "r"(a[0]), "r"(a[1]), "r"(a[2]), "r"(a[3]), "r"(b[0]), "r"(b[1]));
}

// A fragment via ldmatrix: 4 regs in one LDSM.x4.
__device__ __forceinline__ void ldsm_x4(uint32_t a[4], uint32_t addr) {
    asm volatile("ldmatrix.sync.aligned.m8n8.x4.shared.b16 {%0,%1,%2,%3}, [%4];"
                 : "=r"(a[0]), "=r"(a[1]), "=r"(a[2]), "=r"(a[3]) : "r"(addr));
}

// B fragment from permuted weights: one 64-bit load.
__device__ __forceinline__ void load_b(uint32_t b[2], const float* __restrict__ W,
                                       int n0, int kc, int qid, int qlane) {
    const float2 t = *reinterpret_cast<const float2*>(
        W + (size_t)(n0 + qid) * C + kc * 8 + qlane * 2);
    b[0] = __float_as_uint(t.x);
    b[1] = __float_as_uint(t.y);
}

__global__ __launch_bounds__(THREADS, 1) void fused_kernel(
    const float* __restrict__ nmat, const float* __restrict__ s, const float* __restrict__ v,
    const float* __restrict__ bq, const float* __restrict__ bk, const float* __restrict__ bv,
    float* __restrict__ out)
{
    extern __shared__ float sm[];
    float* sA  = sm + SM_A;
    float* sv  = sm + SM_V;
    float* sn  = sm + SM_N;
    float* sbq = sm + SM_BQ;
    float* sbk = sm + SM_BK;
    float* sbv = sm + SM_BV;
    float* stg = sm + SM_STG;
    float* ssc = sm + SM_SC;
    float* sp  = sm + SM_P;
    float* sx  = sm + SM_SX;
    float* red = sm + SM_RED;

    const int i     = blockIdx.x;
    const int tid   = threadIdx.x;
    const int wid   = tid >> 5;
    const int lane  = tid & 31;
    const int qid   = lane >> 2;
    const int qlane = lane & 3;
    const int wc0   = wid * 16;

    const uint32_t aBase = smem_u32(sA)
        + (uint32_t)(((lane & 15) * LDA + ((lane >> 4) << 2)) * 4);

    if (tid < C) {
        sn[tid]  = nmat[(size_t)i * C + tid];
        sbq[tid] = bq[tid];
        sbk[tid] = bk[tid];
        sbv[tid] = bv[tid];
    }

    float m_run = -1e30f, l_run = 0.0f;
    float xr[4] = {0.f, 0.f, 0.f, 0.f};

    for (int jt = 0; jt < NV / MT; jt++) {
        const int j0 = jt * MT;
        __syncthreads();   // prior-tile readers of sA/sv done (also covers init stores)

        // build A[j][c] = tf32(n_i[c]*n_j[c]*s[..]) and v-tile
#pragma unroll
        for (int it = 0; it < MT * (C / 4) / THREADS; it++) {
            const int idx = it * THREADS + tid;
            const int j  = idx >> 6;
            const int c4 = (idx & 63) * 4;
            const float4 n4  = *reinterpret_cast<const float4*>(nmat + (size_t)(j0 + j) * C + c4);
            const float4 s4  = *reinterpret_cast<const float4*>(s + ((size_t)i * NV + j0 + j) * C + c4);
            const float4 sn4 = *reinterpret_cast<const float4*>(sn + c4);
            float4 r;
            r.x = to_tf32(sn4.x * n4.x * s4.x);
            r.y = to_tf32(sn4.y * n4.y * s4.y);
            r.z = to_tf32(sn4.z * n4.z * s4.z);
            r.w = to_tf32(sn4.w * n4.w * s4.w);
            *reinterpret_cast<float4*>(sA + j * LDA + c4) = r;
            const float4 v4 = *reinterpret_cast<const float4*>(v + ((size_t)i * NV + j0 + j) * C + c4);
            *reinterpret_cast<float4*>(sv + j * LDV + c4) = v4;
        }
        __syncthreads();

        // ── single-pass fused Q+K+V GEMM (A fragments loaded ONCE per kc)
        float qacc[4][2][4], kacc[4][2][4], vacc[4][2][4];
#pragma unroll
        for (int mb = 0; mb < 4; mb++)
#pragma unroll
            for (int nb = 0; nb < 2; nb++)
#pragma unroll
                for (int e = 0; e < 4; e++) {
                    qacc[mb][nb][e] = 0.f; kacc[mb][nb][e] = 0.f; vacc[mb][nb][e] = 0.f;
                }
        {
            const float* Wq_ = g_wt;
            const float* Wk_ = g_wt + 1 * C * C;
            const float* Wv_ = g_wt + 2 * C * C;
#pragma unroll 2
            for (int kc = 0; kc < 32; kc++) {
                uint32_t bqf[2][2], bkf[2][2], bvf[2][2];   // single-buffered: 12 regs
                load_b(bqf[0], Wq_, wc0,     kc, qid, qlane);
                load_b(bqf[1], Wq_, wc0 + 8, kc, qid, qlane);
                load_b(bkf[0], Wk_, wc0,     kc, qid, qlane);
                load_b(bkf[1], Wk_, wc0 + 8, kc, qid, qlane);
                load_b(bvf[0], Wv_, wc0,     kc, qid, qlane);
                load_b(bvf[1], Wv_, wc0 + 8, kc, qid, qlane);
#pragma unroll
                for (int mb = 0; mb < 4; mb++) {
                    uint32_t a[4];
                    ldsm_x4(a, aBase + (uint32_t)((mb * 16 * LDA + kc * 8) * 4));
                    mma8(qacc[mb][0], a, bqf[0]);
                    mma8(qacc[mb][1], a, bqf[1]);
                    mma8(kacc[mb][0], a, bkf[0]);
                    mma8(kacc[mb][1], a, bkf[1]);
                    mma8(vacc[mb][0], a, bvf[0]);
                    mma8(vacc[mb][1], a, bvf[1]);
                }
            }
        }

        // ── scores in-register (qacc/kacc die after this)
        {
            float pr[8];
#pragma unroll
            for (int z = 0; z < 8; z++) pr[z] = 0.f;
#pragma unroll
            for (int nb = 0; nb < 2; nb++) {
                const int c0 = wc0 + nb * 8 + 2 * qlane;
                const float bq0 = sbq[c0], bq1 = sbq[c0 + 1];
                const float bk0 = sbk[c0], bk1 = sbk[c0 + 1];
#pragma unroll
                for (int mb = 0; mb < 4; mb++) {
                    const int r0 = mb * 16 + qid;
                    const float2 va = *reinterpret_cast<const float2*>(sv + r0 * LDV + c0);
                    const float2 vb = *reinterpret_cast<const float2*>(sv + (r0 + 8) * LDV + c0);
                    pr[mb * 2 + 0] += (qacc[mb][nb][0] + bq0) * (kacc[mb][nb][0] + bk0) * va.x * va.x
                                    + (qacc[mb][nb][1] + bq1) * (kacc[mb][nb][1] + bk1) * va.y * va.y;
                    pr[mb * 2 + 1] += (qacc[mb][nb][2] + bq0) * (kacc[mb][nb][2] + bk0) * vb.x * vb.x
                                    + (qacc[mb][nb][3] + bq1) * (kacc[mb][nb][3] + bk1) * vb.y * vb.y;
                }
            }
#pragma unroll
            for (int z = 0; z < 8; z++) {
                pr[z] += __shfl_xor_sync(0xffffffffu, pr[z], 1);
                pr[z] += __shfl_xor_sync(0xffffffffu, pr[z], 2);
            }
            if (qlane == 0) {
#pragma unroll
                for (int mb = 0; mb < 4; mb++) {
                    stg[(mb * 16 + qid) * 17 + wid]     = pr[mb * 2 + 0];
                    stg[(mb * 16 + qid + 8) * 17 + wid] = pr[mb * 2 + 1];
                }
            }
        }
        __syncthreads();

        // row-reduce 16 warp partials -> scores
        {
            const int row = tid >> 3, k8 = tid & 7;
            float ssum = stg[row * 17 + k8] + stg[row * 17 + 8 + k8];
            ssum += __shfl_xor_sync(0xffffffffu, ssum, 1);
            ssum += __shfl_xor_sync(0xffffffffu, ssum, 2);
            ssum += __shfl_xor_sync(0xffffffffu, ssum, 4);
            if (k8 == 0) ssc[row] = ssum * 0.0625f;   // 1/sqrt(256)
        }
        __syncthreads();

        // online softmax (replicated)
        {
            float tm = -1e30f;
#pragma unroll 8
            for (int j = 0; j < MT; j++) tm = fmaxf(tm, ssc[j]);
            const float m_new = fmaxf(m_run, tm);
            const float scl = __expf(m_run - m_new);
            l_run *= scl;
#pragma unroll
            for (int z = 0; z < 4; z++) xr[z] *= scl;
            if (tid < MT) sp[tid] = __expf(ssc[tid] - m_new);
            __syncthreads();
            float ls = 0.0f;
#pragma unroll 8
            for (int j = 0; j < MT; j++) ls += sp[j];
            l_run += ls;
            m_run = m_new;
        }

        // ── V epilogue straight from vacc (no second GEMM pass)
        {
#pragma unroll
            for (int nb = 0; nb < 2; nb++) {
                const int c0 = wc0 + nb * 8 + 2 * qlane;
                const float bv0 = sbv[c0], bv1 = sbv[c0 + 1];
                float pc0 = 0.f, pc1 = 0.f;
#pragma unroll
                for (int mb = 0; mb < 4; mb++) {
                    const int r0 = mb * 16 + qid;
                    const float p0 = sp[r0], p1 = sp[r0 + 8];
                    const float2 va = *reinterpret_cast<const float2*>(sv + r0 * LDV + c0);
                    const float2 vb = *reinterpret_cast<const float2*>(sv + (r0 + 8) * LDV + c0);
                    pc0 += p0 * (vacc[mb][nb][0] + bv0) * va.x
                         + p1 * (vacc[mb][nb][2] + bv0) * vb.x;
                    pc1 += p0 * (vacc[mb][nb][1] + bv1) * va.y
                         + p1 * (vacc[mb][nb][3] + bv1) * vb.y;
                }
                pc0 += __shfl_xor_sync(0xffffffffu, pc0, 4);
                pc0 += __shfl_xor_sync(0xffffffffu, pc0, 8);
                pc0 += __shfl_xor_sync(0xffffffffu, pc0, 16);
                pc1 += __shfl_xor_sync(0xffffffffu, pc1, 4);
                pc1 += __shfl_xor_sync(0xffffffffu, pc1, 8);
                pc1 += __shfl_xor_sync(0xffffffffu, pc1, 16);
                xr[nb * 2 + 0] += pc0;
                xr[nb * 2 + 1] += pc1;
            }
        }
    }

    // publish per-warp column results
    if (qid == 0) {
#pragma unroll
        for (int nb = 0; nb < 2; nb++) {
            sx[wc0 + nb * 8 + 2 * qlane]     = xr[nb * 2 + 0];
            sx[wc0 + nb * 8 + 2 * qlane + 1] = xr[nb * 2 + 1];
        }
    }
    __syncthreads();

    // residual + L2 normalize
    float x = 0.0f;
    if (tid < C) x = sx[tid] / l_run + sn[tid];
    float sq = (tid < C) ? x * x : 0.0f;
#pragma unroll
    for (int o = 16; o > 0; o >>= 1) sq += __shfl_xor_sync(0xffffffffu, sq, o);
    if (lane == 0) red[wid] = sq;
    __syncthreads();
    float tot = 0.0f;
#pragma unroll
    for (int w = 0; w < NWARP; w++) tot += red[w];
    if (tid < C) out[(size_t)i * C + tid] = x * rsqrtf(tot);
}

extern "C" void kernel_launch(void* const* d_in, const int* in_sizes, int n_in,
                              void* d_out, int out_size) {
    const float* nmat = (const float*)d_in[0];
    const float* s    = (const float*)d_in[1];
    const float* v    = (const float*)d_in[2];
    const float* Wq   = (const float*)d_in[3];
    const float* bq   = (const float*)d_in[4];
    const float* Wk   = (const float*)d_in[5];
    const float* bk   = (const float*)d_in[6];
    const float* Wv   = (const float*)d_in[7];
    const float* bv   = (const float*)d_in[8];

    prep_weights<<<dim3(32, 3), 256>>>(Wq, Wk, Wv);

    cudaFuncSetAttribute(fused_kernel, cudaFuncAttributeMaxDynamicSharedMemorySize, SMEM_BYTES);
    fused_kernel<<<NV, THREADS, SMEM_BYTES>>>(nmat, s, v, bq, bk, bv, (float*)d_out);
}

// round 14
// speedup vs baseline: 5.1566x; 1.2676x over previous
#include <cuda_runtime.h>
#include <cstdint>
#include <math.h>

namespace {
constexpr int NV = 512;
constexpr int C  = 256;
constexpr int MT = 64;        // j-rows per tile
constexpr int LDA = 260;      // padded smem stride (floats): rows 16B apart mod 128
constexpr int LDV = 260;
constexpr int NWARP = 16;
constexpr int THREADS = 512;

// smem layout (floats)
constexpr int SM_A   = 0;                  // [MT][LDA] tf32 A-tile
constexpr int SM_V   = SM_A + MT * LDA;    // [MT][LDV] v-tile (fp32)
constexpr int SM_N   = SM_V + MT * LDV;    // [C]
constexpr int SM_BQ  = SM_N + C;           // [C]
constexpr int SM_BK  = SM_BQ + C;          // [C]
constexpr int SM_BV  = SM_BK + C;          // [C]
constexpr int SM_STG = SM_BV + C;          // [64][17] score partials per warp
constexpr int SM_SC  = SM_STG + 64 * 17;   // [64] scores
constexpr int SM_P   = SM_SC + 64;         // [64] exp probs
constexpr int SM_SX  = SM_P + 64;          // [C] final x partials
constexpr int SM_RED = SM_SX + C;          // [NWARP]
constexpr int SMEM_FLOATS = SM_RED + NWARP;
constexpr int SMEM_BYTES  = SMEM_FLOATS * 4;   // ~146 KB
}

// Blocked tf32 weights: [mat][n_blk(32)][k_blk(32)][64], each 8x8 tile contiguous.
// Within a tile, lane (qid,qlane) reads its mma B-fragment pair (k=qlane, k=qlane+4)
// at offset qid*8 + qlane*2  -> warp fragment = one contiguous 256-B region.
__device__ float g_wt[3 * C * C];

__device__ __forceinline__ float to_tf32(float x) {
    float y; asm("cvt.rna.tf32.f32 %0, %1;" : "=f"(y) : "f"(x)); return y;
}
__device__ __forceinline__ uint32_t smem_u32(const void* p) {
    uint32_t a;
    asm("{ .reg .u64 t; cvta.to.shared.u64 t, %1; cvt.u32.u64 %0, t; }" : "=r"(a) : "l"(p));
    return a;
}

// One thread handles one 8-col k-block of one weight row.
__global__ __launch_bounds__(256) void prep_weights(
    const float* __restrict__ Wq, const float* __restrict__ Wk, const float* __restrict__ Wv)
{
    const int id  = blockIdx.x * 256 + threadIdx.x;
    const int row = id >> 5, blk = id & 31;
    const float* src = (blockIdx.y == 0) ? Wq : (blockIdx.y == 1 ? Wk : Wv);
    const float* p = src + (size_t)row * C + blk * 8;
    float4 lo = *reinterpret_cast<const float4*>(p);
    float4 hi = *reinterpret_cast<const float4*>(p + 4);
    float4 o0, o1;   // pair-permuted: c0,c0+4,c0+1,c0+5 | c0+2,c0+6,c0+3,c0+7
    o0.x = to_tf32(lo.x); o0.y = to_tf32(hi.x); o0.z = to_tf32(lo.y); o0.w = to_tf32(hi.y);
    o1.x = to_tf32(lo.z); o1.y = to_tf32(hi.z); o1.z = to_tf32(lo.w); o1.w = to_tf32(hi.w);
    // blocked destination: tile (n_blk=row>>3, k_blk=blk), inner row = row&7
    float* dst = g_wt + (size_t)blockIdx.y * C * C
               + ((size_t)(row >> 3) * 32 + blk) * 64 + (row & 7) * 8;
    *reinterpret_cast<float4*>(dst)     = o0;
    *reinterpret_cast<float4*>(dst + 4) = o1;
}

// D += A*B : m16n8k8 tf32.
__device__ __forceinline__ void mma8(float c[4], const uint32_t a[4], const uint32_t b[2]) {
    asm volatile(
        "mma.sync.aligned.m16n8k8.row.col.f32.tf32.tf32.f32 "
        "{%0,%1,%2,%3}, {%4,%5,%6,%7}, {%8,%9}, {%0,%1,%2,%3};"
        : "+f"(c[0]), "+f"(c[1]), "+f"(c[2]), "+f"(c[3])
        : "r"(a[0]), "r"(a[1]), "r"(a[2]), "r"(a[3]), "r"(b[0]), "r"(b[1]));
}

// A fragment via ldmatrix: 4 regs in one LDSM.x4.
__device__ __forceinline__ void ldsm_x4(uint32_t a[4], uint32_t addr) {
    asm volatile("ldmatrix.sync.aligned.m8n8.x4.shared.b16 {%0,%1,%2,%3}, [%4];"
                 : "=r"(a[0]), "=r"(a[1]), "=r"(a[2]), "=r"(a[3]) : "r"(addr));
}

// B fragment from blocked weights: one coalesced 64-bit load at p[kc*64].
__device__ __forceinline__ void load_b2(uint32_t b[2], const float* __restrict__ p, int kc) {
    const float2 t = *reinterpret_cast<const float2*>(p + kc * 64);
    b[0] = __float_as_uint(t.x);
    b[1] = __float_as_uint(t.y);
}

__global__ __launch_bounds__(THREADS, 1) void fused_kernel(
    const float* __restrict__ nmat, const float* __restrict__ s, const float* __restrict__ v,
    const float* __restrict__ bq, const float* __restrict__ bk, const float* __restrict__ bv,
    float* __restrict__ out)
{
    extern __shared__ float sm[];
    float* sA  = sm + SM_A;
    float* sv  = sm + SM_V;
    float* sn  = sm + SM_N;
    float* sbq = sm + SM_BQ;
    float* sbk = sm + SM_BK;
    float* sbv = sm + SM_BV;
    float* stg = sm + SM_STG;
    float* ssc = sm + SM_SC;
    float* sp  = sm + SM_P;
    float* sx  = sm + SM_SX;
    float* red = sm + SM_RED;

    const int i     = blockIdx.x;
    const int tid   = threadIdx.x;
    const int wid   = tid >> 5;
    const int lane  = tid & 31;
    const int qid   = lane >> 2;
    const int qlane = lane & 3;
    const int wc0   = wid * 16;

    const uint32_t aBase = smem_u32(sA)
        + (uint32_t)(((lane & 15) * LDA + ((lane >> 4) << 2)) * 4);

    // 6 blocked-weight fragment pointers (lane offset folded in)
    const int boff = qid * 8 + qlane * 2;
    const float* pq0 = g_wt + (size_t)(wid * 2) * 2048 + boff;       // n_blk = wid*2
    const float* pq1 = pq0 + 2048;                                    // n_blk = wid*2+1
    const float* pk0 = pq0 + 1 * C * C;
    const float* pk1 = pq1 + 1 * C * C;
    const float* pv0 = pq0 + 2 * C * C;
    const float* pv1 = pq1 + 2 * C * C;

    if (tid < C) {
        sn[tid]  = nmat[(size_t)i * C + tid];
        sbq[tid] = bq[tid];
        sbk[tid] = bk[tid];
        sbv[tid] = bv[tid];
    }

    float m_run = -1e30f, l_run = 0.0f;
    float xr[4] = {0.f, 0.f, 0.f, 0.f};

    for (int jt = 0; jt < NV / MT; jt++) {
        const int j0 = jt * MT;
        __syncthreads();   // prior-tile readers of sA/sv done (also covers init stores)

        // build A[j][c] = tf32(n_i[c]*n_j[c]*s[..]) and v-tile
#pragma unroll
        for (int it = 0; it < MT * (C / 4) / THREADS; it++) {
            const int idx = it * THREADS + tid;
            const int j  = idx >> 6;
            const int c4 = (idx & 63) * 4;
            const float4 n4  = *reinterpret_cast<const float4*>(nmat + (size_t)(j0 + j) * C + c4);
            const float4 s4  = *reinterpret_cast<const float4*>(s + ((size_t)i * NV + j0 + j) * C + c4);
            const float4 sn4 = *reinterpret_cast<const float4*>(sn + c4);
            float4 r;
            r.x = to_tf32(sn4.x * n4.x * s4.x);
            r.y = to_tf32(sn4.y * n4.y * s4.y);
            r.z = to_tf32(sn4.z * n4.z * s4.z);
            r.w = to_tf32(sn4.w * n4.w * s4.w);
            *reinterpret_cast<float4*>(sA + j * LDA + c4) = r;
            const float4 v4 = *reinterpret_cast<const float4*>(v + ((size_t)i * NV + j0 + j) * C + c4);
            *reinterpret_cast<float4*>(sv + j * LDV + c4) = v4;
        }
        __syncthreads();

        // ── single-pass fused Q+K+V GEMM (A fragments loaded ONCE per kc)
        float qacc[4][2][4], kacc[4][2][4], vacc[4][2][4];
#pragma unroll
        for (int mb = 0; mb < 4; mb++)
#pragma unroll
            for (int nb = 0; nb < 2; nb++)
#pragma unroll
                for (int e = 0; e < 4; e++) {
                    qacc[mb][nb][e] = 0.f; kacc[mb][nb][e] = 0.f; vacc[mb][nb][e] = 0.f;
                }
        {
#pragma unroll 2
            for (int kc = 0; kc < 32; kc++) {
                uint32_t bqf[2][2], bkf[2][2], bvf[2][2];   // single-buffered: 12 regs
                load_b2(bqf[0], pq0, kc);
                load_b2(bqf[1], pq1, kc);
                load_b2(bkf[0], pk0, kc);
                load_b2(bkf[1], pk1, kc);
                load_b2(bvf[0], pv0, kc);
                load_b2(bvf[1], pv1, kc);
#pragma unroll
                for (int mb = 0; mb < 4; mb++) {
                    uint32_t a[4];
                    ldsm_x4(a, aBase + (uint32_t)((mb * 16 * LDA + kc * 8) * 4));
                    mma8(qacc[mb][0], a, bqf[0]);
                    mma8(qacc[mb][1], a, bqf[1]);
                    mma8(kacc[mb][0], a, bkf[0]);
                    mma8(kacc[mb][1], a, bkf[1]);
                    mma8(vacc[mb][0], a, bvf[0]);
                    mma8(vacc[mb][1], a, bvf[1]);
                }
            }
        }

        // ── scores in-register (qacc/kacc die after this)
        {
            float pr[8];
#pragma unroll
            for (int z = 0; z < 8; z++) pr[z] = 0.f;
#pragma unroll
            for (int nb = 0; nb < 2; nb++) {
                const int c0 = wc0 + nb * 8 + 2 * qlane;
                const float bq0 = sbq[c0], bq1 = sbq[c0 + 1];
                const float bk0 = sbk[c0], bk1 = sbk[c0 + 1];
#pragma unroll
                for (int mb = 0; mb < 4; mb++) {
                    const int r0 = mb * 16 + qid;
                    const float2 va = *reinterpret_cast<const float2*>(sv + r0 * LDV + c0);
                    const float2 vb = *reinterpret_cast<const float2*>(sv + (r0 + 8) * LDV + c0);
                    pr[mb * 2 + 0] += (qacc[mb][nb][0] + bq0) * (kacc[mb][nb][0] + bk0) * va.x * va.x
                                    + (qacc[mb][nb][1] + bq1) * (kacc[mb][nb][1] + bk1) * va.y * va.y;
                    pr[mb * 2 + 1] += (qacc[mb][nb][2] + bq0) * (kacc[mb][nb][2] + bk0) * vb.x * vb.x
                                    + (qacc[mb][nb][3] + bq1) * (kacc[mb][nb][3] + bk1) * vb.y * vb.y;
                }
            }
#pragma unroll
            for (int z = 0; z < 8; z++) {
                pr[z] += __shfl_xor_sync(0xffffffffu, pr[z], 1);
                pr[z] += __shfl_xor_sync(0xffffffffu, pr[z], 2);
            }
            if (qlane == 0) {
#pragma unroll
                for (int mb = 0; mb < 4; mb++) {
                    stg[(mb * 16 + qid) * 17 + wid]     = pr[mb * 2 + 0];
                    stg[(mb * 16 + qid + 8) * 17 + wid] = pr[mb * 2 + 1];
                }
            }
        }
        __syncthreads();

        // row-reduce 16 warp partials -> scores
        {
            const int row = tid >> 3, k8 = tid & 7;
            float ssum = stg[row * 17 + k8] + stg[row * 17 + 8 + k8];
            ssum += __shfl_xor_sync(0xffffffffu, ssum, 1);
            ssum += __shfl_xor_sync(0xffffffffu, ssum, 2);
            ssum += __shfl_xor_sync(0xffffffffu, ssum, 4);
            if (k8 == 0) ssc[row] = ssum * 0.0625f;   // 1/sqrt(256)
        }
        __syncthreads();

        // online softmax (replicated)
        {
            float tm = -1e30f;
#pragma unroll 8
            for (int j = 0; j < MT; j++) tm = fmaxf(tm, ssc[j]);
            const float m_new = fmaxf(m_run, tm);
            const float scl = __expf(m_run - m_new);
            l_run *= scl;
#pragma unroll
            for (int z = 0; z < 4; z++) xr[z] *= scl;
            if (tid < MT) sp[tid] = __expf(ssc[tid] - m_new);
            __syncthreads();
            float ls = 0.0f;
#pragma unroll 8
            for (int j = 0; j < MT; j++) ls += sp[j];
            l_run += ls;
            m_run = m_new;
        }

        // ── V epilogue straight from vacc (no second GEMM pass)
        {
#pragma unroll
            for (int nb = 0; nb < 2; nb++) {
                const int c0 = wc0 + nb * 8 + 2 * qlane;
                const float bv0 = sbv[c0], bv1 = sbv[c0 + 1];
                float pc0 = 0.f, pc1 = 0.f;
#pragma unroll
                for (int mb = 0; mb < 4; mb++) {
                    const int r0 = mb * 16 + qid;
                    const float p0 = sp[r0], p1 = sp[r0 + 8];
                    const float2 va = *reinterpret_cast<const float2*>(sv + r0 * LDV + c0);
                    const float2 vb = *reinterpret_cast<const float2*>(sv + (r0 + 8) * LDV + c0);
                    pc0 += p0 * (vacc[mb][nb][0] + bv0) * va.x
                         + p1 * (vacc[mb][nb][2] + bv0) * vb.x;
                    pc1 += p0 * (vacc[mb][nb][1] + bv1) * va.y
                         + p1 * (vacc[mb][nb][3] + bv1) * vb.y;
                }
                pc0 += __shfl_xor_sync(0xffffffffu, pc0, 4);
                pc0 += __shfl_xor_sync(0xffffffffu, pc0, 8);
                pc0 += __shfl_xor_sync(0xffffffffu, pc0, 16);
                pc1 += __shfl_xor_sync(0xffffffffu, pc1, 4);
                pc1 += __shfl_xor_sync(0xffffffffu, pc1, 8);
                pc1 += __shfl_xor_sync(0xffffffffu, pc1, 16);
                xr[nb * 2 + 0] += pc0;
                xr[nb * 2 + 1] += pc1;
            }
        }
    }

    // publish per-warp column results
    if (qid == 0) {
#pragma unroll
        for (int nb = 0; nb < 2; nb++) {
            sx[wc0 + nb * 8 + 2 * qlane]     = xr[nb * 2 + 0];
            sx[wc0 + nb * 8 + 2 * qlane + 1] = xr[nb * 2 + 1];
        }
    }
    __syncthreads();

    // residual + L2 normalize
    float x = 0.0f;
    if (tid < C) x = sx[tid] / l_run + sn[tid];
    float sq = (tid < C) ? x * x : 0.0f;
#pragma unroll
    for (int o = 16; o > 0; o >>= 1) sq += __shfl_xor_sync(0xffffffffu, sq, o);
    if (lane == 0) red[wid] = sq;
    __syncthreads();
    float tot = 0.0f;
#pragma unroll
    for (int w = 0; w < NWARP; w++) tot += red[w];
    if (tid < C) out[(size_t)i * C + tid] = x * rsqrtf(tot);
}

extern "C" void kernel_launch(void* const* d_in, const int* in_sizes, int n_in,
                              void* d_out, int out_size) {
    const float* nmat = (const float*)d_in[0];
    const float* s    = (const float*)d_in[1];
    const float* v    = (const float*)d_in[2];
    const float* Wq   = (const float*)d_in[3];
    const float* bq   = (const float*)d_in[4];
    const float* Wk   = (const float*)d_in[5];
    const float* bk   = (const float*)d_in[6];
    const float* Wv   = (const float*)d_in[7];
    const float* bv   = (const float*)d_in[8];

    prep_weights<<<dim3(32, 3), 256>>>(Wq, Wk, Wv);

    cudaFuncSetAttribute(fused_kernel, cudaFuncAttributeMaxDynamicSharedMemorySize, SMEM_BYTES);
    fused_kernel<<<NV, THREADS, SMEM_BYTES>>>(nmat, s, v, bq, bk, bv, (float*)d_out);
}